// round 6
// baseline (speedup 1.0000x reference)
#include <cuda_runtime.h>
#include <math.h>
#include <float.h>

#define N1 16384
#define N2 16384
#define G 128
#define NC (G * G)
#define CAPLOG 6
#define CAP (1 << CAPLOG)        // 64 points per cell max (central cell E[n] ~ 23)
#define BOX 6.0f
#define CS (2.0f * BOX / (float)G)   // 0.09375
#define RBLK 64

// Scratch (no allocations allowed -> __device__ globals).
// g_cnt is zero-initialized at module load and re-zeroed by final_kernel at the
// end of every launch, so the invariant "counts are 0 at kernel_launch entry"
// holds for the correctness run and for every graph replay.
__device__ int    g_cnt[NC];
__device__ float2 g_pts[NC * CAP];
__device__ float  g_bsum[RBLK];

__device__ __forceinline__ int cellcoord(float v) {
    int c = (int)floorf((v + BOX) * (1.0f / CS));
    return min(max(c, 0), G - 1);
}

// Bin pos2 points into fixed-capacity grid buckets.
__global__ void __launch_bounds__(256) scatter_kernel(const float* __restrict__ pos2) {
    int i = blockIdx.x * 256 + threadIdx.x;
    if (i < N2) {
        float x = pos2[2 * i];
        float y = pos2[2 * i + 1];
        int c = cellcoord(y) * G + cellcoord(x);
        int slot = atomicAdd(&g_cnt[c], 1);
        if (slot < CAP) g_pts[(c << CAPLOG) + slot] = make_float2(x, y);
    }
}

__device__ __forceinline__ void scan_cell(int cx, int cy, float qx, float qy,
                                          float& best2) {
    int c = cy * G + cx;
    int n = g_cnt[c];
    n = (n > CAP) ? CAP : n;
    const float2* __restrict__ p = &g_pts[c << CAPLOG];
    for (int j = 0; j < n; j++) {
        float2 pt = p[j];
        float dx = qx - pt.x;
        float dy = qy - pt.y;
        float d2 = fmaf(dx, dx, dy * dy);
        best2 = fminf(best2, d2);
    }
}

// Exact NN per query via expanding Chebyshev rings.
// A point in a ring-k cell is at distance >= (k-1)*CS from the query (query
// lies inside its own cell), so once best2 <= ((r-1)*CS)^2 no ring >= r can
// improve the answer.
__global__ void __launch_bounds__(256) query_kernel(const float* __restrict__ pos1) {
    int q = blockIdx.x * 256 + threadIdx.x;
    float qx = pos1[2 * q];
    float qy = pos1[2 * q + 1];
    int cx = cellcoord(qx);
    int cy = cellcoord(qy);

    float best2 = FLT_MAX;
    for (int r = 0; r < G; r++) {
        if (r >= 1) {
            float dm = (float)(r - 1) * CS;
            if (best2 <= dm * dm) break;   // exact termination bound
        }
        int x0 = max(cx - r, 0), x1 = min(cx + r, G - 1);
        int y0 = max(cy - r, 0), y1 = min(cy + r, G - 1);
        for (int yy = y0; yy <= y1; yy++) {
            if (yy == cy - r || yy == cy + r) {
                // full edge row of the ring
                for (int xx = x0; xx <= x1; xx++)
                    scan_cell(xx, yy, qx, qy, best2);
            } else {
                // side columns only
                if (cx - r >= 0)     scan_cell(cx - r, yy, qx, qy, best2);
                if (cx + r <= G - 1) scan_cell(cx + r, yy, qx, qy, best2);
            }
        }
    }

    float d = sqrtf(best2);

    __shared__ float red[256];
    red[threadIdx.x] = d;
    __syncthreads();
    #pragma unroll
    for (int s = 128; s > 0; s >>= 1) {
        if (threadIdx.x < s) red[threadIdx.x] += red[threadIdx.x + s];
        __syncthreads();
    }
    if (threadIdx.x == 0) g_bsum[blockIdx.x] = red[0];
}

// Sum block partials -> mean, and re-zero the cell counters for the next
// invocation (the query phase is fully done at this point).
__global__ void __launch_bounds__(256) final_kernel(float* __restrict__ out) {
    __shared__ float red[RBLK];
    if (threadIdx.x < RBLK) red[threadIdx.x] = g_bsum[threadIdx.x];
    __syncthreads();
    #pragma unroll
    for (int s = RBLK / 2; s > 0; s >>= 1) {
        if (threadIdx.x < s) red[threadIdx.x] += red[threadIdx.x + s];
        __syncthreads();
    }
    if (threadIdx.x == 0) out[0] = red[0] * (1.0f / (float)N1);

    // self-clean counters (16384 ints = 4096 int4)
    int4* __restrict__ z = (int4*)g_cnt;
    #pragma unroll 4
    for (int i = threadIdx.x; i < NC / 4; i += 256)
        z[i] = make_int4(0, 0, 0, 0);
}

extern "C" void kernel_launch(void* const* d_in, const int* in_sizes, int n_in,
                              void* d_out, int out_size) {
    const float* pos1 = (const float*)d_in[0];
    const float* pos2 = (const float*)d_in[1];

    scatter_kernel<<<N2 / 256, 256>>>(pos2);
    query_kernel<<<N1 / 256, 256>>>(pos1);
    final_kernel<<<1, 256>>>((float*)d_out);
}

// round 7
// speedup vs baseline: 3.1010x; 3.1010x over previous
#include <cuda_runtime.h>
#include <math.h>
#include <float.h>

#define N1 16384
#define N2 16384
#define G 128
#define NC (G * G)
#define CAPLOG 6
#define CAP (1 << CAPLOG)            // 64 (central cell E[n] ~ 23, P(>64) ~ 1e-11)
#define BOX 6.0f
#define CS (2.0f * BOX / (float)G)   // 0.09375
#define NB 512
#define TPB 256
#define NWARP (NB * TPB / 32)        // 4096 warps, 4 queries each

// Scratch (no allocations allowed -> __device__ globals). All zero-init at
// module load; block 0 restores everything to zero at the end of each launch
// so graph replays start clean.
__device__ int          g_cnt[NC];
__device__ float2       g_pts[NC * CAP];
__device__ float        g_bsum[NB];
__device__ unsigned int g_bar1;
__device__ unsigned int g_bar2;

__device__ __forceinline__ int cellcoord(float v) {
    int c = (int)floorf((v + BOX) * (1.0f / CS));
    return min(max(c, 0), G - 1);
}

// Software grid barrier. Safe: grid = 512 CTAs, __launch_bounds__(256,4)
// guarantees >= 4 CTAs/SM resident capacity (148*4 = 592 >= 512), so all CTAs
// are wave-1 co-resident and the spin cannot deadlock.
__device__ __forceinline__ void gridbar(unsigned int* bar) {
    __syncthreads();
    if (threadIdx.x == 0) {
        __threadfence();
        unsigned int v = atomicAdd(bar, 1u) + 1u;
        if (v < (unsigned int)NB) {
            while (*(volatile unsigned int*)bar < (unsigned int)NB) {
                __nanosleep(64);
            }
        }
        __threadfence();
    }
    __syncthreads();
}

__device__ __forceinline__ void eval_pt(float2 pt, float qx, float qy, float& best2) {
    float dx = qx - pt.x;
    float dy = qy - pt.y;
    best2 = fminf(best2, fmaf(dx, dx, dy * dy));
}

__global__ void __launch_bounds__(TPB, 4) fused_kernel(
    const float* __restrict__ pos1,
    const float* __restrict__ pos2,
    float* __restrict__ out)
{
    const int lane = threadIdx.x & 31;

    // ---- Phase 1: scatter pos2 into grid buckets (32 pts per CTA) ----
    for (int i = blockIdx.x * TPB + threadIdx.x; i < N2; i += NB * TPB) {
        float2 p = ((const float2*)pos2)[i];
        int c = cellcoord(p.y) * G + cellcoord(p.x);
        int slot = atomicAdd(&g_cnt[c], 1);
        if (slot < CAP) g_pts[(c << CAPLOG) + slot] = p;
    }
    gridbar(&g_bar1);

    // ---- Phase 2: warp-cooperative exact NN queries ----
    const int wid = (blockIdx.x * TPB + threadIdx.x) >> 5;
    float sum = 0.0f;

    for (int q = wid; q < N1; q += NWARP) {
        const float qx = pos1[2 * q];
        const float qy = pos1[2 * q + 1];
        const int cx = cellcoord(qx);
        const int cy = cellcoord(qy);

        float best2 = FLT_MAX;

        // 3x3 neighborhood (rings 0+1), lane-parallel over points per cell.
        // Fully unrolled: 9 independent count loads + point scans -> high MLP.
        #pragma unroll
        for (int dy = -1; dy <= 1; dy++) {
            #pragma unroll
            for (int dx = -1; dx <= 1; dx++) {
                int xx = cx + dx, yy = cy + dy;
                if (xx < 0 || xx >= G || yy < 0 || yy >= G) continue;
                int cell = yy * G + xx;
                int n = min(g_cnt[cell], CAP);
                for (int j = lane; j < n; j += 32)
                    eval_pt(g_pts[(cell << CAPLOG) + j], qx, qy, best2);
            }
        }
        #pragma unroll
        for (int o = 16; o; o >>= 1)
            best2 = fminf(best2, __shfl_xor_sync(0xffffffffu, best2, o));

        // Rare tail path (warp-uniform branch): expand rings, lane-per-cell.
        // A point in a ring-r cell is at distance >= (r-1)*CS.
        if (best2 > CS * CS) {
            for (int r = 2; r < G; r++) {
                float dm = (float)(r - 1) * CS;
                if (best2 <= dm * dm) break;
                int L = 2 * r + 1;
                int ncells = 8 * r;
                float lb2 = best2;
                for (int t = lane; t < ncells; t += 32) {
                    int xx, yy;
                    if (t < L)          { xx = cx - r + t;       yy = cy - r; }
                    else if (t < 2 * L) { xx = cx - r + (t - L); yy = cy + r; }
                    else {
                        int s = t - 2 * L;
                        yy = cy - r + 1 + (s >> 1);
                        xx = (s & 1) ? cx + r : cx - r;
                    }
                    if (xx < 0 || xx >= G || yy < 0 || yy >= G) continue;
                    int cell = yy * G + xx;
                    int n = min(g_cnt[cell], CAP);
                    for (int j = 0; j < n; j++)
                        eval_pt(g_pts[(cell << CAPLOG) + j], qx, qy, lb2);
                }
                best2 = lb2;
                #pragma unroll
                for (int o = 16; o; o >>= 1)
                    best2 = fminf(best2, __shfl_xor_sync(0xffffffffu, best2, o));
            }
        }

        sum += sqrtf(best2);   // identical across all lanes (best2 fully reduced)
    }

    // ---- Per-block deterministic sum (lane 0 of each warp holds warp total) ----
    __shared__ float red[TPB / 32];
    if (lane == 0) red[threadIdx.x >> 5] = sum;
    __syncthreads();
    if (threadIdx.x == 0) {
        float s = 0.0f;
        #pragma unroll
        for (int w = 0; w < TPB / 32; w++) s += red[w];
        g_bsum[blockIdx.x] = s;
    }

    gridbar(&g_bar2);

    // ---- Phase 3: block 0 final sum + state cleanup for next replay ----
    if (blockIdx.x == 0) {
        __shared__ float fr[TPB];
        fr[threadIdx.x] = g_bsum[threadIdx.x] + g_bsum[threadIdx.x + TPB];
        __syncthreads();
        #pragma unroll
        for (int s = TPB / 2; s > 0; s >>= 1) {
            if (threadIdx.x < s) fr[threadIdx.x] += fr[threadIdx.x + s];
            __syncthreads();
        }
        if (threadIdx.x == 0) {
            out[0] = fr[0] * (1.0f / (float)N1);
            g_bar1 = 0;
            g_bar2 = 0;
        }
        // re-zero cell counters (all CTAs are past bar2; only block 0 runs here)
        int4* z = (int4*)g_cnt;
        #pragma unroll 4
        for (int i = threadIdx.x; i < NC / 4; i += TPB)
            z[i] = make_int4(0, 0, 0, 0);
    }
}

extern "C" void kernel_launch(void* const* d_in, const int* in_sizes, int n_in,
                              void* d_out, int out_size) {
    const float* pos1 = (const float*)d_in[0];
    const float* pos2 = (const float*)d_in[1];
    fused_kernel<<<NB, TPB>>>(pos1, pos2, (float*)d_out);
}

// round 8
// speedup vs baseline: 3.1367x; 1.0115x over previous
#include <cuda_runtime.h>
#include <math.h>
#include <float.h>

#define N1 16384
#define N2 16384
#define G 128
#define GH (G + 2)                 // 130: 1-cell halo, hot path needs no bounds checks
#define NCH (GH * GH)              // 16900
#define NCH4 16912                 // padded for int4 zeroing
#define CAPLOG 6
#define CAP (1 << CAPLOG)          // 64 slots (central cell lambda ~ 3.6; huge margin)
#define BOX 6.0f
#define CS (2.0f * BOX / (float)G) // 0.09375
#define NB 512
#define TPB 256
#define NWARP (NB * TPB / 32)      // 4096 warps x 4 queries = 16384 = N1 exactly

// Scratch (no allocations -> __device__ globals). Zero-init at load; the
// last-finishing block re-zeros all state each launch so graph replays are clean.
__device__ int          g_cnt[NCH4];
__device__ float2       g_pts[NCH * CAP];
__device__ float        g_bsum[NB];
__device__ unsigned int g_bar1;
__device__ unsigned int g_done;

// 2-bit packed (dx, dy) for the 9 neighbor cells, t = 0..8: dx = t%3, dy = t/3
#define DXBITS 0x24924u
#define DYBITS 0x2A540u

__device__ __forceinline__ int cellcoord(float v) {
    int c = (int)floorf((v + BOX) * (1.0f / CS));
    return min(max(c, 0), G - 1) + 1;   // 1..G (interior of halo grid)
}

// Software grid barrier. Safe: __launch_bounds__(256,4) -> >=4 CTAs/SM capacity,
// 148*4 = 592 >= 512 launched CTAs, all co-resident in wave 1.
__device__ __forceinline__ void gridbar(unsigned int* bar) {
    __syncthreads();
    if (threadIdx.x == 0) {
        __threadfence();
        if (atomicAdd(bar, 1u) + 1u < (unsigned int)NB) {
            while (*(volatile unsigned int*)bar < (unsigned int)NB) __nanosleep(32);
        }
        __threadfence();
    }
    __syncthreads();
}

__device__ __forceinline__ void scan_cell(int c, float qx, float qy, float& lb2) {
    int n = min(g_cnt[c], CAP);
    const float4* __restrict__ p = (const float4*)&g_pts[c << CAPLOG];
    for (int j = 0; j < n; j += 2) {
        float4 v = p[j >> 1];
        float dx0 = qx - v.x, dy0 = qy - v.y;
        lb2 = fminf(lb2, fmaf(dx0, dx0, dy0 * dy0));
        if (j + 1 < n) {
            float dx1 = qx - v.z, dy1 = qy - v.w;
            lb2 = fminf(lb2, fmaf(dx1, dx1, dy1 * dy1));
        }
    }
}

__global__ void __launch_bounds__(TPB, 4) fused_kernel(
    const float* __restrict__ pos1,
    const float* __restrict__ pos2,
    float* __restrict__ out)
{
    const int lane = threadIdx.x & 31;
    const int s    = lane & 7;                       // sub-lane within 8-lane group
    const unsigned smask = 0xFFu << (lane & 24);     // subgroup shuffle mask
    const int wid = (blockIdx.x * TPB + threadIdx.x) >> 5;

    // Prefetch this subgroup's query (independent of scatter -> hides latency
    // under the barrier). One query per 8-lane subgroup, 4 per warp.
    const int q = wid * 4 + (lane >> 3);             // 0..16383, exact cover
    const float2 qp = ((const float2*)pos1)[q];
    const float qx = qp.x, qy = qp.y;
    const int cx = cellcoord(qx);
    const int cy = cellcoord(qy);

    // ---- Phase 1: scatter pos2 into halo-grid buckets ----
    {
        int i = blockIdx.x * TPB + threadIdx.x;
        if (i < N2) {
            float2 p = ((const float2*)pos2)[i];
            int c = cellcoord(p.y) * GH + cellcoord(p.x);
            int slot = atomicAdd(&g_cnt[c], 1);
            if (slot < CAP) g_pts[(c << CAPLOG) + slot] = p;
        }
    }
    gridbar(&g_bar1);

    // ---- Phase 2: exact NN, 3x3 neighborhood, cell-per-lane ----
    float best2 = FLT_MAX;
    {
        const int base = (cy - 1) * GH + (cx - 1);
        const int off  = (int)((DYBITS >> (2 * s)) & 3u) * GH +
                         (int)((DXBITS >> (2 * s)) & 3u);
        scan_cell(base + off, qx, qy, best2);        // cells t = 0..7
        if (s == 0) scan_cell(base + 2 * GH + 2, qx, qy, best2);  // t = 8
    }
    #pragma unroll
    for (int o = 4; o; o >>= 1)
        best2 = fminf(best2, __shfl_xor_sync(smask, best2, o));

    // ---- Rare tail: expand Chebyshev rings (subgroup-predicated).
    // Points in a ring-r cell are at distance >= (r-1)*CS from the query.
    {
        int r = 2;
        bool active = best2 > CS * CS;
        while (__any_sync(0xffffffffu, active)) {
            if (active) {
                float dm = (float)(r - 1) * CS;
                if (best2 <= dm * dm) {
                    active = false;
                } else {
                    float lb2 = best2;
                    const int L = 2 * r + 1, ncells = 8 * r;
                    for (int t = s; t < ncells; t += 8) {
                        int xx, yy;
                        if (t < L)          { xx = cx - r + t;       yy = cy - r; }
                        else if (t < 2 * L) { xx = cx - r + (t - L); yy = cy + r; }
                        else {
                            int u = t - 2 * L;
                            yy = cy - r + 1 + (u >> 1);
                            xx = (u & 1) ? cx + r : cx - r;
                        }
                        if (xx >= 1 && xx <= G && yy >= 1 && yy <= G)
                            scan_cell(yy * GH + xx, qx, qy, lb2);
                    }
                    best2 = lb2;
                    #pragma unroll
                    for (int o = 4; o; o >>= 1)
                        best2 = fminf(best2, __shfl_xor_sync(smask, best2, o));
                    r++;
                }
            }
        }
    }

    // One contribution per query (sub-lane 0 of each subgroup).
    float sum = (s == 0) ? sqrtf(best2) : 0.0f;

    // ---- Per-block deterministic tree sum ----
    __shared__ float red[TPB];
    red[threadIdx.x] = sum;
    __syncthreads();
    #pragma unroll
    for (int st = TPB / 2; st > 0; st >>= 1) {
        if (threadIdx.x < st) red[threadIdx.x] += red[threadIdx.x + st];
        __syncthreads();
    }

    // ---- Last-block-done: final fixed-order sum + state cleanup ----
    __shared__ bool amlast;
    if (threadIdx.x == 0) {
        g_bsum[blockIdx.x] = red[0];
        __threadfence();
        amlast = (atomicAdd(&g_done, 1u) == (unsigned int)(NB - 1));
    }
    __syncthreads();

    if (amlast) {
        __shared__ float fr[TPB];
        fr[threadIdx.x] = g_bsum[threadIdx.x] + g_bsum[threadIdx.x + TPB];
        __syncthreads();
        #pragma unroll
        for (int st = TPB / 2; st > 0; st >>= 1) {
            if (threadIdx.x < st) fr[threadIdx.x] += fr[threadIdx.x + st];
            __syncthreads();
        }
        if (threadIdx.x == 0) {
            out[0] = fr[0] * (1.0f / (float)N1);
            g_bar1 = 0;
            g_done = 0;
        }
        // re-zero cell counters for the next graph replay
        int4* z = (int4*)g_cnt;
        for (int i = threadIdx.x; i < NCH4 / 4; i += TPB)
            z[i] = make_int4(0, 0, 0, 0);
    }
}

extern "C" void kernel_launch(void* const* d_in, const int* in_sizes, int n_in,
                              void* d_out, int out_size) {
    const float* pos1 = (const float*)d_in[0];
    const float* pos2 = (const float*)d_in[1];
    fused_kernel<<<NB, TPB>>>(pos1, pos2, (float*)d_out);
}

// round 9
// speedup vs baseline: 3.3736x; 1.0755x over previous
#include <cuda_runtime.h>
#include <math.h>
#include <float.h>

#define N1 16384
#define N2 16384
#define G 128
#define GH (G + 2)                 // 130: 1-cell halo, hot 3x3 needs no bounds checks
#define NCH (GH * GH)              // 16900
#define NCH4 16912                 // padded for int4 zeroing
#define CAPLOG 6
#define CAP (1 << CAPLOG)          // 64 slots (central cell lambda ~ 23, P(>64) ~ 1e-11)
#define BOX 6.0f
#define CS (2.0f * BOX / (float)G) // 0.09375
#define NB 512
#define TPB 256

// Scratch (no allocations -> __device__ globals). Zero-init at load; the
// last-finishing block re-zeros all state each launch so graph replays are clean.
__device__ int          g_cnt[NCH4];
__device__ float2       g_pts[NCH * CAP];
__device__ float        g_bsum[NB];
__device__ unsigned int g_bar1;
__device__ unsigned int g_done;

// 2-bit packed (dx, dy) for neighbor cells t = 0..7: dx = t%3, dy = t/3
#define DXBITS 0x24924u
#define DYBITS 0x2A540u

__device__ __forceinline__ int cellcoord(float v) {
    int c = (int)floorf((v + BOX) * (1.0f / CS));
    return min(max(c, 0), G - 1) + 1;   // 1..G (interior of halo grid)
}

// Software grid barrier. Safe: __launch_bounds__(256,4) -> >=4 CTAs/SM capacity,
// 148*4 = 592 >= 512 launched CTAs, all co-resident in wave 1.
__device__ __forceinline__ void gridbar(unsigned int* bar) {
    __syncthreads();
    if (threadIdx.x == 0) {
        __threadfence();
        if (atomicAdd(bar, 1u) + 1u < (unsigned int)NB) {
            while (*(volatile unsigned int*)bar < (unsigned int)NB) __nanosleep(32);
        }
        __threadfence();
    }
    __syncthreads();
}

__device__ __forceinline__ void scan_cell(int c, float qx, float qy, float& lb2) {
    int n = min(g_cnt[c], CAP);
    const float4* __restrict__ p = (const float4*)&g_pts[c << CAPLOG];
    for (int j = 0; j < n; j += 2) {
        float4 v = p[j >> 1];
        float dx0 = qx - v.x, dy0 = qy - v.y;
        lb2 = fminf(lb2, fmaf(dx0, dx0, dy0 * dy0));
        if (j + 1 < n) {
            float dx1 = qx - v.z, dy1 = qy - v.w;
            lb2 = fminf(lb2, fmaf(dx1, dx1, dy1 * dy1));
        }
    }
}

__global__ void __launch_bounds__(TPB, 4) fused_kernel(
    const float* __restrict__ pos1,
    const float* __restrict__ pos2,
    float* __restrict__ out)
{
    const int lane = threadIdx.x & 31;
    const int s    = lane & 7;                       // sub-lane within 8-lane group
    const unsigned smask = 0xFFu << (lane & 24);     // subgroup shuffle mask
    const unsigned FULL  = 0xFFFFFFFFu;
    const int wid = (blockIdx.x * TPB + threadIdx.x) >> 5;

    // One query per 8-lane subgroup, 4 per warp. Prefetch before the barrier.
    const int q = wid * 4 + (lane >> 3);             // 0..16383, exact cover
    const float2 qp = ((const float2*)pos1)[q];
    const float qx = qp.x, qy = qp.y;
    const int cx = cellcoord(qx);
    const int cy = cellcoord(qy);

    // ---- Phase 1: scatter pos2 into halo-grid buckets ----
    {
        int i = blockIdx.x * TPB + threadIdx.x;
        if (i < N2) {
            float2 p = ((const float2*)pos2)[i];
            int c = cellcoord(p.y) * GH + cellcoord(p.x);
            int slot = atomicAdd(&g_cnt[c], 1);
            if (slot < CAP) g_pts[(c << CAPLOG) + slot] = p;
        }
    }
    gridbar(&g_bar1);

    // ---- Phase 2: exact NN, 3x3 neighborhood (rings 0+1), cell-per-lane ----
    float best2 = FLT_MAX;
    {
        const int base = (cy - 1) * GH + (cx - 1);
        const int off  = (int)((DYBITS >> (2 * s)) & 3u) * GH +
                         (int)((DXBITS >> (2 * s)) & 3u);
        scan_cell(base + off, qx, qy, best2);                     // cells 0..7
        if (s == 0) scan_cell(base + 2 * GH + 2, qx, qy, best2);  // cell 8
    }
    #pragma unroll
    for (int o = 4; o; o >>= 1)
        best2 = fminf(best2, __shfl_xor_sync(smask, best2, o));

    // ---- Rare tail: unfinished queries processed FULL-WARP, one at a time,
    // scanning 4-ring annuli per step. A point in ring r is at distance
    // >= (r-1)*CS; after scanning through ring r1 we may stop if
    // best2 <= (r1*CS)^2 (next unscanned ring is r1+1).
    {
        unsigned pend = __ballot_sync(FULL, (s == 0) && (best2 > CS * CS));
        while (pend) {
            const int src = __ffs(pend) - 1;
            pend &= pend - 1;
            const float wqx = __shfl_sync(FULL, qx, src);
            const float wqy = __shfl_sync(FULL, qy, src);
            const int   wcx = __shfl_sync(FULL, cx, src);
            const int   wcy = __shfl_sync(FULL, cy, src);
            float wb2 = __shfl_sync(FULL, best2, src);

            int r0 = 2;
            while (r0 < 2 * G) {
                const float dm = (float)(r0 - 1) * CS;
                if (wb2 <= dm * dm) break;
                const int r1 = r0 + 3;
                const int W  = 2 * r1 + 1;           // full-row width
                const int H  = r1 - r0 + 1;          // band thickness (=4)
                const int A  = 2 * H * W;            // cells in top+bottom bands
                const int w2 = 2 * H;
                const int ncells = A + (2 * r0 - 1) * w2;

                float lb2 = wb2;
                for (int t = lane; t < ncells; t += 32) {
                    int dx, dy;
                    if (t < A) {
                        int row = t / W, col = t - row * W;
                        dy = (row < H) ? (-r1 + row) : (r0 + row - H);
                        dx = col - r1;
                    } else {
                        int u = t - A;
                        int row = u / w2, col = u - row * w2;
                        dy = -r0 + 1 + row;
                        dx = (col < H) ? (-r1 + col) : (r0 + col - H);
                    }
                    int xx = wcx + dx, yy = wcy + dy;
                    if (xx >= 1 && xx <= G && yy >= 1 && yy <= G)
                        scan_cell(yy * GH + xx, wqx, wqy, lb2);
                }
                #pragma unroll
                for (int o = 16; o; o >>= 1)
                    lb2 = fminf(lb2, __shfl_xor_sync(FULL, lb2, o));
                wb2 = lb2;
                r0 = r1 + 1;
            }
            if (lane == src) best2 = wb2;
        }
    }

    // One contribution per query (sub-lane 0 of each subgroup).
    float sum = (s == 0) ? sqrtf(best2) : 0.0f;

    // ---- Per-block deterministic tree sum ----
    __shared__ float red[TPB];
    red[threadIdx.x] = sum;
    __syncthreads();
    #pragma unroll
    for (int st = TPB / 2; st > 0; st >>= 1) {
        if (threadIdx.x < st) red[threadIdx.x] += red[threadIdx.x + st];
        __syncthreads();
    }

    // ---- Last-block-done: final fixed-order sum + state cleanup ----
    __shared__ bool amlast;
    if (threadIdx.x == 0) {
        g_bsum[blockIdx.x] = red[0];
        __threadfence();
        amlast = (atomicAdd(&g_done, 1u) == (unsigned int)(NB - 1));
    }
    __syncthreads();

    if (amlast) {
        __shared__ float fr[TPB];
        fr[threadIdx.x] = g_bsum[threadIdx.x] + g_bsum[threadIdx.x + TPB];
        __syncthreads();
        #pragma unroll
        for (int st = TPB / 2; st > 0; st >>= 1) {
            if (threadIdx.x < st) fr[threadIdx.x] += fr[threadIdx.x + st];
            __syncthreads();
        }
        if (threadIdx.x == 0) {
            out[0] = fr[0] * (1.0f / (float)N1);
            g_bar1 = 0;
            g_done = 0;
        }
        // re-zero cell counters for the next graph replay
        int4* z = (int4*)g_cnt;
        for (int i = threadIdx.x; i < NCH4 / 4; i += TPB)
            z[i] = make_int4(0, 0, 0, 0);
    }
}

extern "C" void kernel_launch(void* const* d_in, const int* in_sizes, int n_in,
                              void* d_out, int out_size) {
    const float* pos1 = (const float*)d_in[0];
    const float* pos2 = (const float*)d_in[1];
    fused_kernel<<<NB, TPB>>>(pos1, pos2, (float*)d_out);
}

// round 10
// speedup vs baseline: 3.7044x; 1.0980x over previous
#include <cuda_runtime.h>
#include <math.h>
#include <float.h>

#define N1 16384
#define N2 16384
#define G 128
#define GH (G + 2)                 // 130: 1-cell halo, no bounds checks in hot path
#define NCH (GH * GH)              // 16900
#define NCH4 16912                 // padded for int4 zeroing
#define CAPLOG 6
#define CAP (1 << CAPLOG)          // 64 slots (central cell lambda ~ 23, P(>64) ~ 1e-13)
#define BOX 6.0f
#define CS (2.0f * BOX / (float)G) // 0.09375
#define NB 512
#define TPB 128                    // 2048 warps x 8 queries = 16384 = N1

// Scratch (no allocations -> __device__ globals). Zero-init at load; last block
// re-zeros all state each launch so graph replays start clean.
__device__ int          g_cnt[NCH4];
__device__ float2       g_pts[NCH * CAP];
__device__ float        g_bsum[NB];
__device__ unsigned int g_bar1;
__device__ unsigned int g_done;

__device__ __forceinline__ int cellcoord(float v) {
    int c = (int)floorf((v + BOX) * (1.0f / CS));
    return min(max(c, 0), G - 1) + 1;   // 1..G (interior of halo grid)
}

// Software grid barrier. Safe: __launch_bounds__(128,8) -> 8 CTAs/SM capacity,
// 148*8 = 1184 >= 512 launched CTAs, all co-resident in wave 1.
__device__ __forceinline__ void gridbar(unsigned int* bar) {
    __syncthreads();
    if (threadIdx.x == 0) {
        __threadfence();
        if (atomicAdd(bar, 1u) + 1u < (unsigned int)NB) {
            while (*(volatile unsigned int*)bar < (unsigned int)NB) __nanosleep(32);
        }
        __threadfence();
    }
    __syncthreads();
}

__device__ __forceinline__ void scan_cell(int c, float qx, float qy, float& lb2) {
    int n = min(g_cnt[c], CAP);
    const float4* __restrict__ p = (const float4*)&g_pts[c << CAPLOG];
    for (int j = 0; j < n; j += 2) {
        float4 v = p[j >> 1];
        float dx0 = qx - v.x, dy0 = qy - v.y;
        lb2 = fminf(lb2, fmaf(dx0, dx0, dy0 * dy0));
        if (j + 1 < n) {
            float dx1 = qx - v.z, dy1 = qy - v.w;
            lb2 = fminf(lb2, fmaf(dx1, dx1, dy1 * dy1));
        }
    }
}

__global__ void __launch_bounds__(TPB, 8) fused_kernel(
    const float* __restrict__ pos1,
    const float* __restrict__ pos2,
    float* __restrict__ out)
{
    const int lane = threadIdx.x & 31;
    const int s    = lane & 3;                       // sub-lane in 4-lane group
    const unsigned gmask = 0xFu << (lane & 28);      // 4-lane group shuffle mask
    const unsigned FULL  = 0xFFFFFFFFu;
    const int wid = (blockIdx.x * TPB + threadIdx.x) >> 5;

    // One query per 4-lane group: 8 per warp, exact cover of N1.
    const int q = wid * 8 + (lane >> 2);
    const float2 qp = ((const float2*)pos1)[q];
    const float qx = qp.x, qy = qp.y;

    // Cell coords + fractional position (for the exact 2x2 termination bound).
    const float tx = (qx + BOX) * (1.0f / CS);
    const float ty = (qy + BOX) * (1.0f / CS);
    const int cx = min(max((int)floorf(tx), 0), G - 1) + 1;
    const int cy = min(max((int)floorf(ty), 0), G - 1) + 1;
    const float fx = tx - floorf(tx);
    const float fy = ty - floorf(ty);
    const int ox = (fx >= 0.5f) ? 1 : -1;            // nearest x-neighbor column
    const int oy = (fy >= 0.5f) ? 1 : -1;
    // Distance from q to the boundary of the scanned 2x2 block (cell units).
    const float mx = fmaxf(fx, 1.0f - fx);
    const float my = fmaxf(fy, 1.0f - fy);
    const float thr = CS * fminf(mx, my);            // in [CS/2, CS]
    const float thr2 = thr * thr;

    // ---- Phase 1: scatter pos2 into halo-grid buckets ----
    {
        int i = blockIdx.x * TPB + threadIdx.x;
        if (i < N2) {
            float2 p = ((const float2*)pos2)[i];
            int c = cellcoord(p.y) * GH + cellcoord(p.x);
            int slot = atomicAdd(&g_cnt[c], 1);
            if (slot < CAP) g_pts[(c << CAPLOG) + slot] = p;
        }
    }
    gridbar(&g_bar1);

    // ---- Phase 2a: nearest 2x2 block, cell-per-lane (one epoch) ----
    float best2 = FLT_MAX;
    {
        // s=0:(0,0)  s=1:(ox,0)  s=2:(0,oy)  s=3:(ox,oy)
        const int dx = (s & 1) ? ox : 0;
        const int dy = (s & 2) ? oy : 0;
        scan_cell((cy + dy) * GH + (cx + dx), qx, qy, best2);
    }
    #pragma unroll
    for (int o = 2; o; o >>= 1)
        best2 = fminf(best2, __shfl_xor_sync(gmask, best2, o));

    // ---- Phase 2b: escalate to full 3x3 if the 2x2 bound fails (rare) ----
    if (__any_sync(FULL, best2 > thr2)) {
        if (best2 > thr2) {
            // the 5 cells of the 3x3 not yet scanned:
            //   t=0..2: (-ox, {-oy,0,oy});  t=3: (0,-oy);  t=4: (ox,-oy)
            #pragma unroll
            for (int t = s; t < 5; t += 4) {
                int dx = (t < 3) ? -ox : ((t == 3) ? 0 : ox);
                int dy = (t < 3) ? ((t - 1) * oy) : -oy;
                scan_cell((cy + dy) * GH + (cx + dx), qx, qy, best2);
            }
        }
        #pragma unroll
        for (int o = 2; o; o >>= 1)
            best2 = fminf(best2, __shfl_xor_sync(gmask, best2, o));
    }

    // ---- Phase 2c: very rare tail — full-warp annulus expansion per query.
    // After the full 3x3, a point in ring r>=2 is at distance >= (r-1)*CS;
    // after scanning through ring r1, stop once best2 <= (r1*CS)^2.
    {
        unsigned pend = __ballot_sync(FULL, (s == 0) && (best2 > CS * CS));
        while (pend) {
            const int src = __ffs(pend) - 1;
            pend &= pend - 1;
            const float wqx = __shfl_sync(FULL, qx, src);
            const float wqy = __shfl_sync(FULL, qy, src);
            const int   wcx = __shfl_sync(FULL, cx, src);
            const int   wcy = __shfl_sync(FULL, cy, src);
            float wb2 = __shfl_sync(FULL, best2, src);

            int r0 = 2;
            while (r0 < 2 * G) {
                const float dm = (float)(r0 - 1) * CS;
                if (wb2 <= dm * dm) break;
                const int r1 = r0 + 3;
                const int W  = 2 * r1 + 1;           // full-row width
                const int H  = r1 - r0 + 1;          // band thickness (=4)
                const int A  = 2 * H * W;            // top+bottom band cells
                const int w2 = 2 * H;
                const int ncells = A + (2 * r0 - 1) * w2;

                float lb2 = wb2;
                for (int t = lane; t < ncells; t += 32) {
                    int dx, dy;
                    if (t < A) {
                        int row = t / W, col = t - row * W;
                        dy = (row < H) ? (-r1 + row) : (r0 + row - H);
                        dx = col - r1;
                    } else {
                        int u = t - A;
                        int row = u / w2, col = u - row * w2;
                        dy = -r0 + 1 + row;
                        dx = (col < H) ? (-r1 + col) : (r0 + col - H);
                    }
                    int xx = wcx + dx, yy = wcy + dy;
                    if (xx >= 1 && xx <= G && yy >= 1 && yy <= G)
                        scan_cell(yy * GH + xx, wqx, wqy, lb2);
                }
                #pragma unroll
                for (int o = 16; o; o >>= 1)
                    lb2 = fminf(lb2, __shfl_xor_sync(FULL, lb2, o));
                wb2 = lb2;
                r0 = r1 + 1;
            }
            if (lane == src) best2 = wb2;
        }
    }

    // One contribution per query (sub-lane 0 of each group).
    float sum = (s == 0) ? sqrtf(best2) : 0.0f;

    // ---- Per-block deterministic tree sum ----
    __shared__ float red[TPB];
    red[threadIdx.x] = sum;
    __syncthreads();
    #pragma unroll
    for (int st = TPB / 2; st > 0; st >>= 1) {
        if (threadIdx.x < st) red[threadIdx.x] += red[threadIdx.x + st];
        __syncthreads();
    }

    // ---- Last-block-done: final fixed-order sum + state cleanup ----
    __shared__ bool amlast;
    if (threadIdx.x == 0) {
        g_bsum[blockIdx.x] = red[0];
        __threadfence();
        amlast = (atomicAdd(&g_done, 1u) == (unsigned int)(NB - 1));
    }
    __syncthreads();

    if (amlast) {
        __shared__ float fr[TPB];
        fr[threadIdx.x] = (g_bsum[threadIdx.x]         + g_bsum[threadIdx.x + TPB]) +
                          (g_bsum[threadIdx.x + 2*TPB] + g_bsum[threadIdx.x + 3*TPB]);
        __syncthreads();
        #pragma unroll
        for (int st = TPB / 2; st > 0; st >>= 1) {
            if (threadIdx.x < st) fr[threadIdx.x] += fr[threadIdx.x + st];
            __syncthreads();
        }
        if (threadIdx.x == 0) {
            out[0] = fr[0] * (1.0f / (float)N1);
            g_bar1 = 0;
            g_done = 0;
        }
        // re-zero cell counters for the next graph replay
        int4* z = (int4*)g_cnt;
        for (int i = threadIdx.x; i < NCH4 / 4; i += TPB)
            z[i] = make_int4(0, 0, 0, 0);
    }
}

extern "C" void kernel_launch(void* const* d_in, const int* in_sizes, int n_in,
                              void* d_out, int out_size) {
    const float* pos1 = (const float*)d_in[0];
    const float* pos2 = (const float*)d_in[1];
    fused_kernel<<<NB, TPB>>>(pos1, pos2, (float*)d_out);
}